// round 4
// baseline (speedup 1.0000x reference)
#include <cuda_runtime.h>
#include <stdint.h>

#define QBINS 313
#define QL    156            // low half-warp: q in [0,156); high: [156,312) + peel q=312
#define HWC   9216           // 96*96
#define MTOT  294912
#define TPB   128
#define NBLK  (MTOT / TPB)   // 2304 (128 pixels per block: 2 threads share 2 pixels)

__device__ float    g_partial[NBLK];
__device__ unsigned g_count = 0;

typedef unsigned long long u64;
typedef unsigned int       u32;

// ---- packed f32x2 helpers (Blackwell FFMA2 path) ----
__device__ __forceinline__ u64 pk(float a, float b) {
    u64 r; asm("mov.b64 %0,{%1,%2};" : "=l"(r) : "f"(a), "f"(b)); return r;
}
__device__ __forceinline__ void upkf(u64 v, float& a, float& b) {
    asm("mov.b64 {%0,%1},%2;" : "=f"(a), "=f"(b) : "l"(v));
}
__device__ __forceinline__ void upki(u64 v, u32& a, u32& b) {
    asm("mov.b64 {%0,%1},%2;" : "=r"(a), "=r"(b) : "l"(v));
}
__device__ __forceinline__ u64 pki(u32 a, u32 b) {
    u64 r; asm("mov.b64 %0,{%1,%2};" : "=l"(r) : "r"(a), "r"(b)); return r;
}
__device__ __forceinline__ u64 f2mul(u64 a, u64 b) {
    u64 r; asm("mul.rn.f32x2 %0,%1,%2;" : "=l"(r) : "l"(a), "l"(b)); return r;
}
__device__ __forceinline__ u64 f2add(u64 a, u64 b) {
    u64 r; asm("add.rn.f32x2 %0,%1,%2;" : "=l"(r) : "l"(a), "l"(b)); return r;
}
__device__ __forceinline__ u64 f2fma(u64 a, u64 b, u64 c) {
    u64 r; asm("fma.rn.f32x2 %0,%1,%2,%3;" : "=l"(r) : "l"(a), "l"(b), "l"(c)); return r;
}

// sorted top-5 insert (uint keys, smallest-5), 9 IMNMX
__device__ __forceinline__ void ins5(u32& k0, u32& k1, u32& k2, u32& k3, u32& k4, u32 key) {
    u32 lo, hi;
    k4 = min(k4, key);
    lo = min(k3, k4); hi = max(k3, k4); k3 = lo; k4 = hi;
    lo = min(k2, k3); hi = max(k2, k3); k2 = lo; k3 = hi;
    lo = min(k1, k2); hi = max(k1, k2); k1 = lo; k2 = hi;
    lo = min(k0, k1); hi = max(k0, k1); k0 = lo; k1 = hi;
}

__global__ void __launch_bounds__(TPB)
loss_main(const float* __restrict__ pred,      // (B, Q, H, W)
          const float* __restrict__ tgt,       // (B, 2, H, W)
          const float* __restrict__ centers,   // (Q, 2)
          const float* __restrict__ cw,        // (Q,)
          float* __restrict__ out)
{
    __shared__ float4 s_c[QBINS];     // (cx, cy, |c|^2/2, class_weight)
    __shared__ float  s_red[TPB / 32];
    __shared__ float  s_fin[TPB];
    __shared__ bool   s_last;

    const int tid = threadIdx.x;
    for (int i = tid; i < QBINS; i += TPB) {
        float2 c = reinterpret_cast<const float2*>(centers)[i];
        float h = fmaf(0.5f * c.x, c.x, 0.5f * c.y * c.y);
        s_c[i] = make_float4(c.x, c.y, h, cw[i]);
    }
    __syncthreads();

    const int lane = tid & 31;
    const int wid  = tid >> 5;
    const bool hiH = (lane >= 16);
    const int qbase = hiH ? QL : 0;

    // each half-warp pair (lane L, L+16) shares pixels m0, m0+1
    const int gw  = blockIdx.x * (TPB / 32) + wid;
    const int m0  = gw * 32 + 2 * (lane & 15);
    const int b   = m0 / HWC;                  // block covers 128 contiguous pixels; same b
    const int rem = m0 - b * HWC;

    const float2 av = *reinterpret_cast<const float2*>(tgt + (size_t)(2 * b)     * HWC + rem);
    const float2 bv = *reinterpret_cast<const float2*>(tgt + (size_t)(2 * b + 1) * HWC + rem);
    float aa[2] = {av.x * 128.f, av.y * 128.f};
    float bb[2] = {bv.x * 128.f, bv.y * 128.f};
    float up[2];                 // |p|^2/2 + 0.5 (positive key, fine quantization)
    #pragma unroll
    for (int p = 0; p < 2; ++p)
        up[p] = fmaf(0.5f * aa[p], aa[p], fmaf(0.5f * bb[p], bb[p], 0.5f));

    // top-5 keys per pixel: (float_bits(d2/2+0.5) & ~0x1FF) | q   (uint-monotone in d2)
    u32 k0[2], k1[2], k2[2], k3[2], k4[2];
    #pragma unroll
    for (int p = 0; p < 2; ++p) { k0[p]=k1[p]=k2[p]=k3[p]=k4[p]=0xFFFFFFFFu; }

    const float*  gbase = pred + (size_t)b * QBINS * HWC + rem;
    const float2* p2    = reinterpret_cast<const float2*>(gbase);
    const float2* p2q   = p2 + (size_t)qbase * (HWC / 2);

    const u64 L2E = pk(1.4426950408889634f, 1.4426950408889634f);
    const u64 CB  = pk(12582912.0f, 12582912.0f);
    const u64 CNB = pk(-12582912.0f, -12582912.0f);
    const u64 M1  = pk(-1.0f, -1.0f);
    const u64 C5  = pk(1.3333558146e-3f, 1.3333558146e-3f);
    const u64 C4  = pk(9.6181291076e-3f, 9.6181291076e-3f);
    const u64 C3  = pk(5.5504108665e-2f, 5.5504108665e-2f);
    const u64 C2  = pk(2.4022650696e-1f, 2.4022650696e-1f);
    const u64 C1  = pk(6.9314718056e-1f, 6.9314718056e-1f);
    const u64 C0  = pk(1.0f, 1.0f);

    u64 S01 = 0ull;   // packed fp32 partial softmax sums (pixel0, pixel1)

    // ---- fused pass over this half-warp's q range ----
    #pragma unroll 4
    for (int j = 0; j < QL; ++j) {
        float2 v = p2q[(size_t)j * (HWC / 2)];
        float4 c = s_c[qbase + j];
        #pragma unroll
        for (int p = 0; p < 2; ++p) {
            float e = fmaf(-aa[p], c.x, fmaf(-bb[p], c.y, c.z)) + up[p];  // d2/2 + 0.5
            u32 key = (__float_as_uint(e) & 0xFFFFFE00u) | (u32)(qbase + j);
            ins5(k0[p], k1[p], k2[p], k3[p], k4[p], key);
        }
        // packed exp for both pixels (fma pipe)
        u64 T = f2mul(pk(v.x, v.y), L2E);
        u64 Z = f2add(T, CB);
        u64 W = f2add(Z, CNB);              // rint(t)
        u64 R = f2fma(W, M1, T);            // t - rint(t)
        u64 P = f2fma(C5, R, C4);
        P = f2fma(P, R, C3);
        P = f2fma(P, R, C2);
        P = f2fma(P, R, C1);
        P = f2fma(P, R, C0);
        u32 zi0, zi1, pi0, pi1;
        upki(Z, zi0, zi1); upki(P, pi0, pi1);
        S01 = f2add(S01, pki(pi0 + (zi0 << 23), pi1 + (zi1 << 23)));
    }

    // peel q = 312 (high half only; 157th iteration)
    if (hiH) {
        const int q = 312;
        float2 v = p2[(size_t)q * (HWC / 2)];
        float4 c = s_c[q];
        #pragma unroll
        for (int p = 0; p < 2; ++p) {
            float e = fmaf(-aa[p], c.x, fmaf(-bb[p], c.y, c.z)) + up[p];
            u32 key = (__float_as_uint(e) & 0xFFFFFE00u) | (u32)q;
            ins5(k0[p], k1[p], k2[p], k3[p], k4[p], key);
        }
        u64 T = f2mul(pk(v.x, v.y), L2E);
        u64 Z = f2add(T, CB);
        u64 W = f2add(Z, CNB);
        u64 R = f2fma(W, M1, T);
        u64 P = f2fma(C5, R, C4);
        P = f2fma(P, R, C3);
        P = f2fma(P, R, C2);
        P = f2fma(P, R, C1);
        P = f2fma(P, R, C0);
        u32 zi0, zi1, pi0, pi1;
        upki(Z, zi0, zi1); upki(P, pi0, pi1);
        S01 = f2add(S01, pki(pi0 + (zi0 << 23), pi1 + (zi1 << 23)));
    }

    // ---- merge halves (lane L <-> L+16): sums + top-5 (disjoint q => no dup keys) ----
    {
        u32 s0, s1;
        upki(S01, s0, s1);
        u32 t0 = __shfl_xor_sync(0xFFFFFFFFu, s0, 16);
        u32 t1 = __shfl_xor_sync(0xFFFFFFFFu, s1, 16);
        S01 = f2add(S01, pki(t0, t1));
    }
    #pragma unroll
    for (int p = 0; p < 2; ++p) {
        u32 o0 = __shfl_xor_sync(0xFFFFFFFFu, k0[p], 16);
        u32 o1 = __shfl_xor_sync(0xFFFFFFFFu, k1[p], 16);
        u32 o2 = __shfl_xor_sync(0xFFFFFFFFu, k2[p], 16);
        u32 o3 = __shfl_xor_sync(0xFFFFFFFFu, k3[p], 16);
        u32 o4 = __shfl_xor_sync(0xFFFFFFFFu, k4[p], 16);
        ins5(k0[p], k1[p], k2[p], k3[p], k4[p], o0);
        ins5(k0[p], k1[p], k2[p], k3[p], k4[p], o1);
        ins5(k0[p], k1[p], k2[p], k3[p], k4[p], o2);
        ins5(k0[p], k1[p], k2[p], k3[p], k4[p], o3);
        ins5(k0[p], k1[p], k2[p], k3[p], k4[p], o4);
    }

    // ---- epilogue: low lane handles pixel 0, high lane pixel 1 ----
    const int p = hiH ? 1 : 0;
    float Sp0, Sp1;
    upkf(S01, Sp0, Sp1);
    float S = hiH ? Sp1 : Sp0;

    u32 kk[5] = {k0[p], k1[p], k2[p], k3[p], k4[p]};
    float wk[5];
    int   idx[5];
    float wsum = 0.f;
    #pragma unroll
    for (int j = 0; j < 5; ++j) {
        idx[j] = (int)(kk[j] & 511u);
        float4 c = s_c[idx[j]];
        float da = aa[p] - c.x;
        float db = bb[p] - c.y;
        float d2 = fmaf(da, da, db * db);
        float w  = __expf(-0.02f * d2);     // exp(-d2/(2*sigma^2)), sigma=5
        wk[j] = w;
        wsum += w;
    }
    float inv = 1.0f / (wsum + 1e-8f);
    float dot = 0.f;
    #pragma unroll
    for (int j = 0; j < 5; ++j) {
        float x = __ldg(gbase + (size_t)idx[j] * HWC + p);
        dot = fmaf(wk[j], x, dot);
    }
    float lse  = __logf(S);
    float pw   = s_c[k0[p] & 511u].w;
    float part = (lse * (wsum * inv) - dot * inv) * pw;

    // ---- deterministic block reduction ----
    #pragma unroll
    for (int o = 16; o > 0; o >>= 1)
        part += __shfl_down_sync(0xFFFFFFFFu, part, o);
    if (lane == 0) s_red[wid] = part;
    __syncthreads();

    if (tid == 0) {
        float bsum = 0.f;
        #pragma unroll
        for (int w = 0; w < TPB / 32; ++w) bsum += s_red[w];
        g_partial[blockIdx.x] = bsum;
        __threadfence();
        unsigned t = atomicAdd(&g_count, 1u);
        s_last = (t == NBLK - 1);
    }
    __syncthreads();

    // ---- last block finalizes (deterministic fixed-order tree) ----
    if (s_last) {
        float v = 0.f;
        #pragma unroll
        for (int base = 0; base < NBLK; base += TPB)
            v += g_partial[base + tid];
        s_fin[tid] = v;
        __syncthreads();
        #pragma unroll
        for (int s = TPB / 2; s > 0; s >>= 1) {
            if (tid < s) s_fin[tid] += s_fin[tid + s];
            __syncthreads();
        }
        if (tid == 0) {
            out[0] = s_fin[0] * (1.0f / (float)MTOT);
            g_count = 0;   // reset for next graph replay
        }
    }
}

extern "C" void kernel_launch(void* const* d_in, const int* in_sizes, int n_in,
                              void* d_out, int out_size) {
    const float* pred    = (const float*)d_in[0];   // (32,313,96,96)
    const float* tgt     = (const float*)d_in[1];   // (32,2,96,96)
    const float* centers = (const float*)d_in[2];   // (313,2)
    const float* cw      = (const float*)d_in[3];   // (313,)
    (void)in_sizes; (void)n_in; (void)out_size;

    loss_main<<<NBLK, TPB>>>(pred, tgt, centers, cw, (float*)d_out);
}

// round 5
// speedup vs baseline: 1.1484x; 1.1484x over previous
#include <cuda_runtime.h>
#include <stdint.h>

#define QBINS 313
#define HWC   9216           // 96*96
#define MTOT  294912
#define TPB   128
#define NBLK  (MTOT / TPB)   // 2304, one pixel per thread
#define GDIM  64
#define NCELL (GDIM * GDIM)
#define MAXC  64

__device__ unsigned short g_list[NCELL * MAXC];
__device__ int            g_cnt[NCELL];
__device__ float          g_partial[NBLK];
__device__ unsigned       g_count = 0;

typedef unsigned long long u64;
typedef unsigned int       u32;

// ---- packed f32x2 helpers (Blackwell FFMA2 path) ----
__device__ __forceinline__ u64 pk(float a, float b) {
    u64 r; asm("mov.b64 %0,{%1,%2};" : "=l"(r) : "f"(a), "f"(b)); return r;
}
__device__ __forceinline__ void upkf(u64 v, float& a, float& b) {
    asm("mov.b64 {%0,%1},%2;" : "=f"(a), "=f"(b) : "l"(v));
}
__device__ __forceinline__ void upki(u64 v, u32& a, u32& b) {
    asm("mov.b64 {%0,%1},%2;" : "=r"(a), "=r"(b) : "l"(v));
}
__device__ __forceinline__ u64 pki(u32 a, u32 b) {
    u64 r; asm("mov.b64 %0,{%1,%2};" : "=l"(r) : "r"(a), "r"(b)); return r;
}
__device__ __forceinline__ u64 f2mul(u64 a, u64 b) {
    u64 r; asm("mul.rn.f32x2 %0,%1,%2;" : "=l"(r) : "l"(a), "l"(b)); return r;
}
__device__ __forceinline__ u64 f2add(u64 a, u64 b) {
    u64 r; asm("add.rn.f32x2 %0,%1,%2;" : "=l"(r) : "l"(a), "l"(b)); return r;
}
__device__ __forceinline__ u64 f2fma(u64 a, u64 b, u64 c) {
    u64 r; asm("fma.rn.f32x2 %0,%1,%2,%3;" : "=l"(r) : "l"(a), "l"(b), "l"(c)); return r;
}

// scalar fast exp (fma pipe), for the peeled q=312
__device__ __forceinline__ float fexp(float x) {
    float t = x * 1.4426950408889634f;
    float z = __fadd_rn(t, 12582912.0f);
    int   n = __float_as_int(z);
    float r = __fsub_rn(t, __fsub_rn(z, 12582912.0f));
    float p = 1.3333558146e-3f;
    p = fmaf(p, r, 9.6181291076e-3f);
    p = fmaf(p, r, 5.5504108665e-2f);
    p = fmaf(p, r, 2.4022650696e-1f);
    p = fmaf(p, r, 6.9314718056e-1f);
    p = fmaf(p, r, 1.0f);
    return __int_as_float(__float_as_int(p) + (n << 23));
}

// sorted top-5 insert (uint keys, smallest-5), 9 IMNMX
__device__ __forceinline__ void ins5(u32& k0, u32& k1, u32& k2, u32& k3, u32& k4, u32 key) {
    u32 lo, hi;
    k4 = min(k4, key);
    lo = min(k3, k4); hi = max(k3, k4); k3 = lo; k4 = hi;
    lo = min(k2, k3); hi = max(k2, k3); k2 = lo; k3 = hi;
    lo = min(k1, k2); hi = max(k1, k2); k1 = lo; k2 = hi;
    lo = min(k0, k1); hi = max(k0, k1); k0 = lo; k1 = hi;
}

// ---- precompute: per-cell candidate lists (exact superset of any point's top-5) ----
// For cell center cc, half-diagonal r: c in top-5 of p in cell => |c-cc| <= d5(cc)+2r.
__global__ void build_grid(const float* __restrict__ centers) {
    __shared__ float2 sc[QBINS];
    for (int i = threadIdx.x; i < QBINS; i += blockDim.x)
        sc[i] = reinterpret_cast<const float2*>(centers)[i];
    __syncthreads();
    int cell = blockIdx.x * blockDim.x + threadIdx.x;
    if (cell >= NCELL) return;
    int cy = cell >> 6, cx = cell & 63;
    float cca = -126.f + 4.f * cx;          // cell covers [-128+4cx, -128+4cx+4)
    float ccb = -126.f + 4.f * cy;

    float d0 = 3.4e38f, d1 = 3.4e38f, d2m = 3.4e38f, d3 = 3.4e38f, d4 = 3.4e38f;
    for (int q = 0; q < QBINS; ++q) {
        float da = cca - sc[q].x, db = ccb - sc[q].y;
        float d = fmaf(da, da, db * db);
        float lo, hi;
        d4 = fminf(d4, d);
        lo = fminf(d3, d4);  hi = fmaxf(d3, d4);  d3 = lo;  d4 = hi;
        lo = fminf(d2m, d3); hi = fmaxf(d2m, d3); d2m = lo; d3 = hi;
        lo = fminf(d1, d2m); hi = fmaxf(d1, d2m); d1 = lo;  d2m = hi;
        lo = fminf(d0, d1);  hi = fmaxf(d0, d1);  d0 = lo;  d1 = hi;
    }
    float R  = sqrtf(d4) + 5.6569f + 0.01f;   // d5(cc) + 2r (+eps)
    float R2 = R * R;
    int n = 0;
    for (int q = 0; q < QBINS; ++q) {
        float da = cca - sc[q].x, db = ccb - sc[q].y;
        float d = fmaf(da, da, db * db);
        if (d <= R2 && n < MAXC) g_list[cell * MAXC + n++] = (unsigned short)q;
    }
    g_cnt[cell] = n;
}

__global__ void __launch_bounds__(TPB, 12)
loss_main(const float* __restrict__ pred,      // (B, Q, H, W)
          const float* __restrict__ tgt,       // (B, 2, H, W)
          const float* __restrict__ centers,   // (Q, 2)
          const float* __restrict__ cw,        // (Q,)
          float* __restrict__ out)
{
    __shared__ float4 s_c[QBINS];     // (cx, cy, |c|^2/2, class_weight)
    __shared__ float  s_red[TPB / 32];
    __shared__ float  s_fin[TPB];
    __shared__ bool   s_last;

    const int tid = threadIdx.x;
    for (int i = tid; i < QBINS; i += TPB) {
        float2 c = reinterpret_cast<const float2*>(centers)[i];
        float h = fmaf(0.5f * c.x, c.x, 0.5f * c.y * c.y);
        s_c[i] = make_float4(c.x, c.y, h, cw[i]);
    }
    __syncthreads();

    const int m   = blockIdx.x * TPB + tid;    // one pixel per thread
    const int b   = m / HWC;
    const int rem = m - b * HWC;

    const float a  = tgt[(size_t)(2 * b)     * HWC + rem] * 128.f;
    const float bb = tgt[(size_t)(2 * b + 1) * HWC + rem] * 128.f;
    const float up = fmaf(0.5f * a, a, fmaf(0.5f * bb, bb, 0.5f));

    // ---- selection over the (tiny) cell candidate list ----
    int cx = min(max((int)floorf((a  + 128.f) * 0.25f), 0), GDIM - 1);
    int cy = min(max((int)floorf((bb + 128.f) * 0.25f), 0), GDIM - 1);
    int cell = cy * GDIM + cx;
    int n = g_cnt[cell];
    const unsigned short* lst = g_list + cell * MAXC;

    u32 k0 = 0xFFFFFFFFu, k1 = 0xFFFFFFFFu, k2 = 0xFFFFFFFFu,
        k3 = 0xFFFFFFFFu, k4 = 0xFFFFFFFFu;
    for (int j = 0; j < n; ++j) {
        int q = lst[j];
        float4 c = s_c[q];
        float e = fmaf(-a, c.x, fmaf(-bb, c.y, c.z)) + up;   // d2/2 + 0.5
        u32 key = (__float_as_uint(e) & 0xFFFFFE00u) | (u32)q;
        ins5(k0, k1, k2, k3, k4, key);
    }

    // ---- soft-encode weights (exact d2), gather 5 logits ----
    const float* gb = pred + (size_t)b * QBINS * HWC + rem;
    u32 kk[5] = {k0, k1, k2, k3, k4};
    float wk[5];
    int   idx[5];
    float wsum = 0.f;
    #pragma unroll
    for (int j = 0; j < 5; ++j) {
        idx[j] = (int)(kk[j] & 511u);
        float4 c = s_c[idx[j]];
        float da = a - c.x;
        float db = bb - c.y;
        float d2 = fmaf(da, da, db * db);
        float w  = __expf(-0.02f * d2);     // exp(-d2/(2*sigma^2)), sigma=5
        wk[j] = w;
        wsum += w;
    }
    float inv = 1.0f / (wsum + 1e-8f);
    float dot = 0.f;
    #pragma unroll
    for (int j = 0; j < 5; ++j) {
        float x = __ldg(gb + (size_t)idx[j] * HWC);
        dot = fmaf(wk[j], x, dot);
    }
    float pw   = s_c[k0 & 511u].w;
    float coef = (wsum * inv) * pw;          // multiplies log(S)
    float pre  = -(dot * inv) * pw;          // constant part

    // ---- streaming softmax denominator: all 313 logits, packed exp over q-pairs ----
    const u64 L2E = pk(1.4426950408889634f, 1.4426950408889634f);
    const u64 CB  = pk(12582912.0f, 12582912.0f);
    const u64 CNB = pk(-12582912.0f, -12582912.0f);
    const u64 M1  = pk(-1.0f, -1.0f);
    const u64 C5  = pk(1.3333558146e-3f, 1.3333558146e-3f);
    const u64 C4  = pk(9.6181291076e-3f, 9.6181291076e-3f);
    const u64 C3  = pk(5.5504108665e-2f, 5.5504108665e-2f);
    const u64 C2  = pk(2.4022650696e-1f, 2.4022650696e-1f);
    const u64 C1  = pk(6.9314718056e-1f, 6.9314718056e-1f);
    const u64 C0  = pk(1.0f, 1.0f);

    u64 S01 = 0ull;
    #pragma unroll 4
    for (int j = 0; j < QBINS / 2; ++j) {    // 156 iterations, q = 2j, 2j+1
        float v0 = __ldcs(gb + (size_t)(2 * j)     * HWC);
        float v1 = __ldcs(gb + (size_t)(2 * j + 1) * HWC);
        u64 T = f2mul(pk(v0, v1), L2E);
        u64 Z = f2add(T, CB);
        u64 W = f2add(Z, CNB);               // rint(t)
        u64 R = f2fma(W, M1, T);             // t - rint(t), in [-0.5,0.5]
        u64 P = f2fma(C5, R, C4);
        P = f2fma(P, R, C3);
        P = f2fma(P, R, C2);
        P = f2fma(P, R, C1);
        P = f2fma(P, R, C0);
        u32 zi0, zi1, pi0, pi1;
        upki(Z, zi0, zi1); upki(P, pi0, pi1);
        S01 = f2add(S01, pki(pi0 + (zi0 << 23), pi1 + (zi1 << 23)));
    }
    float Sl, Sh;
    upkf(S01, Sl, Sh);
    float S = Sl + Sh + fexp(__ldcs(gb + (size_t)(QBINS - 1) * HWC));

    float part = fmaf(coef, __logf(S), pre);

    // ---- deterministic block reduction ----
    const int lane = tid & 31, wid = tid >> 5;
    #pragma unroll
    for (int o = 16; o > 0; o >>= 1)
        part += __shfl_down_sync(0xFFFFFFFFu, part, o);
    if (lane == 0) s_red[wid] = part;
    __syncthreads();

    if (tid == 0) {
        float bsum = 0.f;
        #pragma unroll
        for (int w = 0; w < TPB / 32; ++w) bsum += s_red[w];
        g_partial[blockIdx.x] = bsum;
        __threadfence();
        unsigned t = atomicAdd(&g_count, 1u);
        s_last = (t == NBLK - 1);
    }
    __syncthreads();

    if (s_last) {
        float v = 0.f;
        #pragma unroll
        for (int base = 0; base < NBLK; base += TPB)
            v += g_partial[base + tid];
        s_fin[tid] = v;
        __syncthreads();
        #pragma unroll
        for (int s = TPB / 2; s > 0; s >>= 1) {
            if (tid < s) s_fin[tid] += s_fin[tid + s];
            __syncthreads();
        }
        if (tid == 0) {
            out[0] = s_fin[0] * (1.0f / (float)MTOT);
            g_count = 0;   // reset for next graph replay
        }
    }
}

extern "C" void kernel_launch(void* const* d_in, const int* in_sizes, int n_in,
                              void* d_out, int out_size) {
    const float* pred    = (const float*)d_in[0];   // (32,313,96,96)
    const float* tgt     = (const float*)d_in[1];   // (32,2,96,96)
    const float* centers = (const float*)d_in[2];   // (313,2)
    const float* cw      = (const float*)d_in[3];   // (313,)
    (void)in_sizes; (void)n_in; (void)out_size;

    build_grid<<<NCELL / TPB, TPB>>>(centers);
    loss_main<<<NBLK, TPB>>>(pred, tgt, centers, cw, (float*)d_out);
}

// round 6
// speedup vs baseline: 1.4346x; 1.2493x over previous
#include <cuda_runtime.h>
#include <stdint.h>

#define QBINS 313
#define HWC   9216           // 96*96
#define MTOT  294912
#define TPB   128
#define PPT   2
#define NBLK  (MTOT / (TPB * PPT))   // 1152 -> single wave at 8 CTAs/SM
#define GDIM  64
#define NCELL (GDIM * GDIM)
#define MAXC  64

__device__ unsigned short g_list[NCELL * MAXC];
__device__ int            g_cnt[NCELL];
__device__ float          g_partial[NBLK];
__device__ unsigned       g_count = 0;

typedef unsigned long long u64;
typedef unsigned int       u32;

// ---- packed f32x2 helpers (Blackwell FFMA2 path) ----
__device__ __forceinline__ u64 pk(float a, float b) {
    u64 r; asm("mov.b64 %0,{%1,%2};" : "=l"(r) : "f"(a), "f"(b)); return r;
}
__device__ __forceinline__ void upkf(u64 v, float& a, float& b) {
    asm("mov.b64 {%0,%1},%2;" : "=f"(a), "=f"(b) : "l"(v));
}
__device__ __forceinline__ void upki(u64 v, u32& a, u32& b) {
    asm("mov.b64 {%0,%1},%2;" : "=r"(a), "=r"(b) : "l"(v));
}
__device__ __forceinline__ u64 pki(u32 a, u32 b) {
    u64 r; asm("mov.b64 %0,{%1,%2};" : "=l"(r) : "r"(a), "r"(b)); return r;
}
__device__ __forceinline__ u64 f2mul(u64 a, u64 b) {
    u64 r; asm("mul.rn.f32x2 %0,%1,%2;" : "=l"(r) : "l"(a), "l"(b)); return r;
}
__device__ __forceinline__ u64 f2add(u64 a, u64 b) {
    u64 r; asm("add.rn.f32x2 %0,%1,%2;" : "=l"(r) : "l"(a), "l"(b)); return r;
}
__device__ __forceinline__ u64 f2fma(u64 a, u64 b, u64 c) {
    u64 r; asm("fma.rn.f32x2 %0,%1,%2,%3;" : "=l"(r) : "l"(a), "l"(b), "l"(c)); return r;
}

// sorted top-5 insert, uint keys (9 IMNMX)
__device__ __forceinline__ void ins5(u32& k0, u32& k1, u32& k2, u32& k3, u32& k4, u32 key) {
    u32 lo, hi;
    k4 = min(k4, key);
    lo = min(k3, k4); hi = max(k3, k4); k3 = lo; k4 = hi;
    lo = min(k2, k3); hi = max(k2, k3); k2 = lo; k3 = hi;
    lo = min(k1, k2); hi = max(k1, k2); k1 = lo; k2 = hi;
    lo = min(k0, k1); hi = max(k0, k1); k0 = lo; k1 = hi;
}

// sorted top-5 insert, float distances (9 FMNMX)
__device__ __forceinline__ void ins5f(float& d0, float& d1, float& d2, float& d3, float& d4, float d) {
    float lo, hi;
    d4 = fminf(d4, d);
    lo = fminf(d3, d4); hi = fmaxf(d3, d4); d3 = lo; d4 = hi;
    lo = fminf(d2, d3); hi = fmaxf(d2, d3); d2 = lo; d3 = hi;
    lo = fminf(d1, d2); hi = fmaxf(d1, d2); d1 = lo; d2 = hi;
    lo = fminf(d0, d1); hi = fmaxf(d0, d1); d0 = lo; d1 = hi;
}

// ---- precompute: per-cell candidate lists, warp per cell ----
// For cell center cc, half-diag r=2.828: c in top-5 of any p in cell => |c-cc| <= d5(cc)+2r.
__global__ void build_grid(const float* __restrict__ centers) {
    __shared__ float2 sc[QBINS];
    for (int i = threadIdx.x; i < QBINS; i += blockDim.x)
        sc[i] = reinterpret_cast<const float2*>(centers)[i];
    __syncthreads();

    const int lane = threadIdx.x & 31;
    const int cell = (blockIdx.x * blockDim.x + threadIdx.x) >> 5;   // warp id = cell
    if (cell >= NCELL) return;
    const int cy = cell >> 6, cx = cell & 63;
    const float cca = -126.f + 4.f * cx;
    const float ccb = -126.f + 4.f * cy;

    // lane-local top-5 distances over q = lane, lane+32, ...
    float d0 = 3.4e38f, d1 = 3.4e38f, d2 = 3.4e38f, d3 = 3.4e38f, d4 = 3.4e38f;
    for (int q = lane; q < QBINS; q += 32) {
        float da = cca - sc[q].x, db = ccb - sc[q].y;
        ins5f(d0, d1, d2, d3, d4, fmaf(da, da, db * db));
    }
    // warp butterfly merge (all lanes converge to global top-5)
    #pragma unroll
    for (int off = 16; off > 0; off >>= 1) {
        float e0 = __shfl_xor_sync(0xFFFFFFFFu, d0, off);
        float e1 = __shfl_xor_sync(0xFFFFFFFFu, d1, off);
        float e2 = __shfl_xor_sync(0xFFFFFFFFu, d2, off);
        float e3 = __shfl_xor_sync(0xFFFFFFFFu, d3, off);
        float e4 = __shfl_xor_sync(0xFFFFFFFFu, d4, off);
        ins5f(d0, d1, d2, d3, d4, e0);
        ins5f(d0, d1, d2, d3, d4, e1);
        ins5f(d0, d1, d2, d3, d4, e2);
        ins5f(d0, d1, d2, d3, d4, e3);
        ins5f(d0, d1, d2, d3, d4, e4);
    }
    const float R  = sqrtf(d4) + 5.6569f + 0.01f;   // d5(cc) + 2r (+eps)
    const float R2 = R * R;

    // ballot compaction: list in ascending q order
    int base = 0;
    for (int r = 0; r * 32 < QBINS; ++r) {
        int q = r * 32 + lane;
        bool pred = false;
        if (q < QBINS) {
            float da = cca - sc[q].x, db = ccb - sc[q].y;
            pred = fmaf(da, da, db * db) <= R2;
        }
        u32 mask = __ballot_sync(0xFFFFFFFFu, pred);
        int pos = base + __popc(mask & ((1u << lane) - 1u));
        if (pred && pos < MAXC) g_list[cell * MAXC + pos] = (unsigned short)q;
        base += __popc(mask);
    }
    if (lane == 0) g_cnt[cell] = min(base, MAXC);
}

// per-pixel selection + soft-encode epilogue -> (coef, pre):  part = coef*log(S) + pre
__device__ __forceinline__ void pixel_prep(float a, float bb, const float* __restrict__ gb,
                                           const float4* __restrict__ s_c,
                                           float& coef, float& pre)
{
    const float up = fmaf(0.5f * a, a, fmaf(0.5f * bb, bb, 0.5f));
    int cx = min(max((int)floorf((a  + 128.f) * 0.25f), 0), GDIM - 1);
    int cy = min(max((int)floorf((bb + 128.f) * 0.25f), 0), GDIM - 1);
    int cell = cy * GDIM + cx;
    int n = g_cnt[cell];
    const unsigned short* lst = g_list + cell * MAXC;

    u32 k0 = 0xFFFFFFFFu, k1 = 0xFFFFFFFFu, k2 = 0xFFFFFFFFu,
        k3 = 0xFFFFFFFFu, k4 = 0xFFFFFFFFu;
    for (int j = 0; j < n; ++j) {
        int q = lst[j];
        float4 c = s_c[q];
        float e = fmaf(-a, c.x, fmaf(-bb, c.y, c.z)) + up;   // d2/2 + 0.5
        ins5(k0, k1, k2, k3, k4, (__float_as_uint(e) & 0xFFFFFE00u) | (u32)q);
    }

    u32 kk[5] = {k0, k1, k2, k3, k4};
    float wk[5];
    int   idx[5];
    float wsum = 0.f;
    #pragma unroll
    for (int j = 0; j < 5; ++j) {
        idx[j] = (int)(kk[j] & 511u);
        float4 c = s_c[idx[j]];
        float da = a - c.x;
        float db = bb - c.y;
        float d2 = fmaf(da, da, db * db);
        float w  = __expf(-0.02f * d2);     // exp(-d2/(2*sigma^2)), sigma=5
        wk[j] = w;
        wsum += w;
    }
    float inv = 1.0f / (wsum + 1e-8f);
    float dot = 0.f;
    #pragma unroll
    for (int j = 0; j < 5; ++j) {
        float x = __ldg(gb + (size_t)idx[j] * HWC);
        dot = fmaf(wk[j], x, dot);
    }
    float pw = s_c[k0 & 511u].w;
    coef = (wsum * inv) * pw;
    pre  = -(dot * inv) * pw;
}

__global__ void __launch_bounds__(TPB, 8)
loss_main(const float* __restrict__ pred,      // (B, Q, H, W)
          const float* __restrict__ tgt,       // (B, 2, H, W)
          const float* __restrict__ centers,   // (Q, 2)
          const float* __restrict__ cw,        // (Q,)
          float* __restrict__ out)
{
    __shared__ float4 s_c[QBINS];     // (cx, cy, |c|^2/2, class_weight)
    __shared__ float  s_red[TPB / 32];
    __shared__ float  s_fin[TPB];
    __shared__ bool   s_last;

    const int tid = threadIdx.x;
    for (int i = tid; i < QBINS; i += TPB) {
        float2 c = reinterpret_cast<const float2*>(centers)[i];
        float h = fmaf(0.5f * c.x, c.x, 0.5f * c.y * c.y);
        s_c[i] = make_float4(c.x, c.y, h, cw[i]);
    }
    __syncthreads();

    const int m0  = (blockIdx.x * TPB + tid) * PPT;   // two adjacent pixels
    const int b   = m0 / HWC;                         // block = 256 contiguous pixels, same b
    const int rem = m0 - b * HWC;

    const float2 av = *reinterpret_cast<const float2*>(tgt + (size_t)(2 * b)     * HWC + rem);
    const float2 bv = *reinterpret_cast<const float2*>(tgt + (size_t)(2 * b + 1) * HWC + rem);
    const float a0 = av.x * 128.f, a1 = av.y * 128.f;
    const float b0 = bv.x * 128.f, b1 = bv.y * 128.f;

    const float* gb = pred + (size_t)b * QBINS * HWC + rem;

    float coef0, pre0, coef1, pre1;
    pixel_prep(a0, b0, gb,     s_c, coef0, pre0);
    pixel_prep(a1, b1, gb + 1, s_c, coef1, pre1);

    // ---- streaming softmax denominators for both pixels (float2 per q) ----
    const u64 L2E = pk(1.4426950408889634f, 1.4426950408889634f);
    const u64 CB  = pk(12582912.0f, 12582912.0f);
    const u64 CNB = pk(-12582912.0f, -12582912.0f);
    const u64 M1  = pk(-1.0f, -1.0f);
    const u64 C5  = pk(1.3333558146e-3f, 1.3333558146e-3f);
    const u64 C4  = pk(9.6181291076e-3f, 9.6181291076e-3f);
    const u64 C3  = pk(5.5504108665e-2f, 5.5504108665e-2f);
    const u64 C2  = pk(2.4022650696e-1f, 2.4022650696e-1f);
    const u64 C1  = pk(6.9314718056e-1f, 6.9314718056e-1f);
    const u64 C0  = pk(1.0f, 1.0f);

    const float2* p2 = reinterpret_cast<const float2*>(gb);
    u64 S01 = 0ull;
    #pragma unroll 8
    for (int q = 0; q < QBINS; ++q) {
        float2 v = __ldcs(p2 + (size_t)q * (HWC / 2));
        u64 T = f2mul(pk(v.x, v.y), L2E);
        u64 Z = f2add(T, CB);
        u64 W = f2add(Z, CNB);               // rint(t)
        u64 R = f2fma(W, M1, T);             // t - rint(t), in [-0.5,0.5]
        u64 P = f2fma(C5, R, C4);
        P = f2fma(P, R, C3);
        P = f2fma(P, R, C2);
        P = f2fma(P, R, C1);
        P = f2fma(P, R, C0);
        u32 zi0, zi1, pi0, pi1;
        upki(Z, zi0, zi1); upki(P, pi0, pi1);
        S01 = f2add(S01, pki(pi0 + (zi0 << 23), pi1 + (zi1 << 23)));
    }
    float S0, S1;
    upkf(S01, S0, S1);

    float part = fmaf(coef0, __logf(S0), pre0) + fmaf(coef1, __logf(S1), pre1);

    // ---- deterministic block reduction ----
    const int lane = tid & 31, wid = tid >> 5;
    #pragma unroll
    for (int o = 16; o > 0; o >>= 1)
        part += __shfl_down_sync(0xFFFFFFFFu, part, o);
    if (lane == 0) s_red[wid] = part;
    __syncthreads();

    if (tid == 0) {
        float bsum = 0.f;
        #pragma unroll
        for (int w = 0; w < TPB / 32; ++w) bsum += s_red[w];
        g_partial[blockIdx.x] = bsum;
        __threadfence();
        unsigned t = atomicAdd(&g_count, 1u);
        s_last = (t == NBLK - 1);
    }
    __syncthreads();

    if (s_last) {
        float v = 0.f;
        #pragma unroll
        for (int base = 0; base < NBLK; base += TPB)
            v += g_partial[base + tid];
        s_fin[tid] = v;
        __syncthreads();
        #pragma unroll
        for (int s = TPB / 2; s > 0; s >>= 1) {
            if (tid < s) s_fin[tid] += s_fin[tid + s];
            __syncthreads();
        }
        if (tid == 0) {
            out[0] = s_fin[0] * (1.0f / (float)MTOT);
            g_count = 0;   // reset for next graph replay
        }
    }
}

extern "C" void kernel_launch(void* const* d_in, const int* in_sizes, int n_in,
                              void* d_out, int out_size) {
    const float* pred    = (const float*)d_in[0];   // (32,313,96,96)
    const float* tgt     = (const float*)d_in[1];   // (32,2,96,96)
    const float* centers = (const float*)d_in[2];   // (313,2)
    const float* cw      = (const float*)d_in[3];   // (313,)
    (void)in_sizes; (void)n_in; (void)out_size;

    build_grid<<<(NCELL * 32) / 256, 256>>>(centers);
    loss_main<<<NBLK, TPB>>>(pred, tgt, centers, cw, (float*)d_out);
}

// round 7
// speedup vs baseline: 1.4691x; 1.0240x over previous
#include <cuda_runtime.h>
#include <stdint.h>

#define QBINS 313
#define HWC   9216           // 96*96
#define MTOT  294912
#define TPB   128
#define PPT   4
#define NBLK  (MTOT / (TPB * PPT))   // 576
#define GDIM  32
#define NCELL (GDIM * GDIM)
#define MAXC  64

__device__ unsigned short g_list[NCELL * MAXC];
__device__ int            g_cnt[NCELL];
__device__ float          g_partial[NBLK];
__device__ unsigned       g_count = 0;

typedef unsigned long long u64;
typedef unsigned int       u32;

// ---- packed f32x2 helpers (Blackwell FFMA2 path) ----
__device__ __forceinline__ u64 pk(float a, float b) {
    u64 r; asm("mov.b64 %0,{%1,%2};" : "=l"(r) : "f"(a), "f"(b)); return r;
}
__device__ __forceinline__ void upkf(u64 v, float& a, float& b) {
    asm("mov.b64 {%0,%1},%2;" : "=f"(a), "=f"(b) : "l"(v));
}
__device__ __forceinline__ void upki(u64 v, u32& a, u32& b) {
    asm("mov.b64 {%0,%1},%2;" : "=r"(a), "=r"(b) : "l"(v));
}
__device__ __forceinline__ u64 pki(u32 a, u32 b) {
    u64 r; asm("mov.b64 %0,{%1,%2};" : "=l"(r) : "r"(a), "r"(b)); return r;
}
__device__ __forceinline__ u64 f2mul(u64 a, u64 b) {
    u64 r; asm("mul.rn.f32x2 %0,%1,%2;" : "=l"(r) : "l"(a), "l"(b)); return r;
}
__device__ __forceinline__ u64 f2add(u64 a, u64 b) {
    u64 r; asm("add.rn.f32x2 %0,%1,%2;" : "=l"(r) : "l"(a), "l"(b)); return r;
}
__device__ __forceinline__ u64 f2fma(u64 a, u64 b, u64 c) {
    u64 r; asm("fma.rn.f32x2 %0,%1,%2,%3;" : "=l"(r) : "l"(a), "l"(b), "l"(c)); return r;
}

// sorted top-5 insert, uint keys (9 IMNMX)
__device__ __forceinline__ void ins5(u32& k0, u32& k1, u32& k2, u32& k3, u32& k4, u32 key) {
    u32 lo, hi;
    k4 = min(k4, key);
    lo = min(k3, k4); hi = max(k3, k4); k3 = lo; k4 = hi;
    lo = min(k2, k3); hi = max(k2, k3); k2 = lo; k3 = hi;
    lo = min(k1, k2); hi = max(k1, k2); k1 = lo; k2 = hi;
    lo = min(k0, k1); hi = max(k0, k1); k0 = lo; k1 = hi;
}

// sorted top-5 insert, float distances (9 FMNMX)
__device__ __forceinline__ void ins5f(float& d0, float& d1, float& d2, float& d3, float& d4, float d) {
    float lo, hi;
    d4 = fminf(d4, d);
    lo = fminf(d3, d4); hi = fmaxf(d3, d4); d3 = lo; d4 = hi;
    lo = fminf(d2, d3); hi = fmaxf(d2, d3); d2 = lo; d3 = hi;
    lo = fminf(d1, d2); hi = fmaxf(d1, d2); d1 = lo; d2 = hi;
    lo = fminf(d0, d1); hi = fmaxf(d0, d1); d0 = lo; d1 = hi;
}

// ---- precompute: per-cell candidate lists, warp per cell ----
// cell side 8, half-diag r=5.657: c in top-5 of any p in cell => |c-cc| <= d5(cc)+2r.
__global__ void build_grid(const float* __restrict__ centers) {
    __shared__ float2 sc[QBINS];
    for (int i = threadIdx.x; i < QBINS; i += blockDim.x)
        sc[i] = reinterpret_cast<const float2*>(centers)[i];
    __syncthreads();

    const int lane = threadIdx.x & 31;
    const int cell = (blockIdx.x * blockDim.x + threadIdx.x) >> 5;   // warp id = cell
    if (cell >= NCELL) return;
    const int cy = cell >> 5, cx = cell & 31;
    const float cca = -124.f + 8.f * cx;
    const float ccb = -124.f + 8.f * cy;

    float d0 = 3.4e38f, d1 = 3.4e38f, d2 = 3.4e38f, d3 = 3.4e38f, d4 = 3.4e38f;
    for (int q = lane; q < QBINS; q += 32) {
        float da = cca - sc[q].x, db = ccb - sc[q].y;
        ins5f(d0, d1, d2, d3, d4, fmaf(da, da, db * db));
    }
    #pragma unroll
    for (int off = 16; off > 0; off >>= 1) {
        float e0 = __shfl_xor_sync(0xFFFFFFFFu, d0, off);
        float e1 = __shfl_xor_sync(0xFFFFFFFFu, d1, off);
        float e2 = __shfl_xor_sync(0xFFFFFFFFu, d2, off);
        float e3 = __shfl_xor_sync(0xFFFFFFFFu, d3, off);
        float e4 = __shfl_xor_sync(0xFFFFFFFFu, d4, off);
        ins5f(d0, d1, d2, d3, d4, e0);
        ins5f(d0, d1, d2, d3, d4, e1);
        ins5f(d0, d1, d2, d3, d4, e2);
        ins5f(d0, d1, d2, d3, d4, e3);
        ins5f(d0, d1, d2, d3, d4, e4);
    }
    const float R  = sqrtf(d4) + 11.3138f + 0.01f;   // d5(cc) + 2r (+eps)
    const float R2 = R * R;

    int base = 0;
    for (int r = 0; r * 32 < QBINS; ++r) {
        int q = r * 32 + lane;
        bool pred = false;
        if (q < QBINS) {
            float da = cca - sc[q].x, db = ccb - sc[q].y;
            pred = fmaf(da, da, db * db) <= R2;
        }
        u32 mask = __ballot_sync(0xFFFFFFFFu, pred);
        int pos = base + __popc(mask & ((1u << lane) - 1u));
        if (pred && pos < MAXC) g_list[cell * MAXC + pos] = (unsigned short)q;
        base += __popc(mask);
    }
    if (lane == 0) g_cnt[cell] = min(base, MAXC);
}

// per-pixel selection + soft-encode epilogue -> (coef, pre):  part = coef*log(S) + pre
__device__ __forceinline__ void pixel_prep(float a, float bb, const float* __restrict__ gb,
                                           const float4* __restrict__ s_c,
                                           float& coef, float& pre)
{
    const float up = fmaf(0.5f * a, a, fmaf(0.5f * bb, bb, 0.5f));
    int cx = min(max((int)floorf((a  + 128.f) * 0.125f), 0), GDIM - 1);
    int cy = min(max((int)floorf((bb + 128.f) * 0.125f), 0), GDIM - 1);
    int cell = cy * GDIM + cx;
    int n = g_cnt[cell];
    const unsigned short* lst = g_list + cell * MAXC;

    u32 k0 = 0xFFFFFFFFu, k1 = 0xFFFFFFFFu, k2 = 0xFFFFFFFFu,
        k3 = 0xFFFFFFFFu, k4 = 0xFFFFFFFFu;
    for (int j = 0; j < n; ++j) {
        int q = lst[j];
        float4 c = s_c[q];
        float e = fmaf(-a, c.x, fmaf(-bb, c.y, c.z)) + up;   // d2/2 + 0.5
        ins5(k0, k1, k2, k3, k4, (__float_as_uint(e) & 0xFFFFFE00u) | (u32)q);
    }

    u32 kk[5] = {k0, k1, k2, k3, k4};
    float wk[5];
    int   idx[5];
    float wsum = 0.f;
    #pragma unroll
    for (int j = 0; j < 5; ++j) {
        idx[j] = (int)(kk[j] & 511u);
        float4 c = s_c[idx[j]];
        float da = a - c.x;
        float db = bb - c.y;
        float d2 = fmaf(da, da, db * db);
        float w  = __expf(-0.02f * d2);     // exp(-d2/(2*sigma^2)), sigma=5
        wk[j] = w;
        wsum += w;
    }
    float inv = 1.0f / (wsum + 1e-8f);
    float dot = 0.f;
    #pragma unroll
    for (int j = 0; j < 5; ++j) {
        float x = __ldg(gb + (size_t)idx[j] * HWC);
        dot = fmaf(wk[j], x, dot);
    }
    float pw = s_c[k0 & 511u].w;
    coef = (wsum * inv) * pw;
    pre  = -(dot * inv) * pw;
}

struct ExpC {
    u64 L2E, CB, CNB, M1, C5, C4, C3, C2, C1, C0;
};

__device__ __forceinline__ void expacc(float4 v, u64& S01, u64& S23, const ExpC& K) {
    {
        u64 T = f2mul(pk(v.x, v.y), K.L2E);
        u64 Z = f2add(T, K.CB);
        u64 W = f2add(Z, K.CNB);
        u64 R = f2fma(W, K.M1, T);
        u64 P = f2fma(K.C5, R, K.C4);
        P = f2fma(P, R, K.C3);
        P = f2fma(P, R, K.C2);
        P = f2fma(P, R, K.C1);
        P = f2fma(P, R, K.C0);
        u32 zi0, zi1, pi0, pi1;
        upki(Z, zi0, zi1); upki(P, pi0, pi1);
        S01 = f2add(S01, pki(pi0 + (zi0 << 23), pi1 + (zi1 << 23)));
    }
    {
        u64 T = f2mul(pk(v.z, v.w), K.L2E);
        u64 Z = f2add(T, K.CB);
        u64 W = f2add(Z, K.CNB);
        u64 R = f2fma(W, K.M1, T);
        u64 P = f2fma(K.C5, R, K.C4);
        P = f2fma(P, R, K.C3);
        P = f2fma(P, R, K.C2);
        P = f2fma(P, R, K.C1);
        P = f2fma(P, R, K.C0);
        u32 zi0, zi1, pi0, pi1;
        upki(Z, zi0, zi1); upki(P, pi0, pi1);
        S23 = f2add(S23, pki(pi0 + (zi0 << 23), pi1 + (zi1 << 23)));
    }
}

__global__ void __launch_bounds__(TPB, 4)
loss_main(const float* __restrict__ pred,      // (B, Q, H, W)
          const float* __restrict__ tgt,       // (B, 2, H, W)
          const float* __restrict__ centers,   // (Q, 2)
          const float* __restrict__ cw,        // (Q,)
          float* __restrict__ out)
{
    __shared__ float4 s_c[QBINS];     // (cx, cy, |c|^2/2, class_weight)
    __shared__ float  s_red[TPB / 32];
    __shared__ float  s_fin[TPB];
    __shared__ bool   s_last;

    const int tid = threadIdx.x;
    for (int i = tid; i < QBINS; i += TPB) {
        float2 c = reinterpret_cast<const float2*>(centers)[i];
        float h = fmaf(0.5f * c.x, c.x, 0.5f * c.y * c.y);
        s_c[i] = make_float4(c.x, c.y, h, cw[i]);
    }
    __syncthreads();

    const int m0  = (blockIdx.x * TPB + tid) * PPT;   // four adjacent pixels
    const int b   = m0 / HWC;                         // block = 512 contiguous pixels, same b
    const int rem = m0 - b * HWC;

    const float4 av = *reinterpret_cast<const float4*>(tgt + (size_t)(2 * b)     * HWC + rem);
    const float4 bv = *reinterpret_cast<const float4*>(tgt + (size_t)(2 * b + 1) * HWC + rem);
    const float aa[4] = {av.x * 128.f, av.y * 128.f, av.z * 128.f, av.w * 128.f};
    const float bb[4] = {bv.x * 128.f, bv.y * 128.f, bv.z * 128.f, bv.w * 128.f};

    const float* gb = pred + (size_t)b * QBINS * HWC + rem;

    float coef[4], pre[4];
    #pragma unroll
    for (int p = 0; p < 4; ++p)
        pixel_prep(aa[p], bb[p], gb + p, s_c, coef[p], pre[p]);

    ExpC K;
    K.L2E = pk(1.4426950408889634f, 1.4426950408889634f);
    K.CB  = pk(12582912.0f, 12582912.0f);
    K.CNB = pk(-12582912.0f, -12582912.0f);
    K.M1  = pk(-1.0f, -1.0f);
    K.C5  = pk(1.3333558146e-3f, 1.3333558146e-3f);
    K.C4  = pk(9.6181291076e-3f, 9.6181291076e-3f);
    K.C3  = pk(5.5504108665e-2f, 5.5504108665e-2f);
    K.C2  = pk(2.4022650696e-1f, 2.4022650696e-1f);
    K.C1  = pk(6.9314718056e-1f, 6.9314718056e-1f);
    K.C0  = pk(1.0f, 1.0f);

    // ---- streaming softmax denominators, explicit 2-stage prefetch pipeline ----
    const float4* p4 = reinterpret_cast<const float4*>(gb);
    u64 S01 = 0ull, S23 = 0ull;

    float4 buf[4];
    #pragma unroll
    for (int j = 0; j < 4; ++j)
        buf[j] = __ldcs(p4 + (size_t)j * (HWC / 4));

    for (int base = 0; base <= 304; base += 4) {     // 77 iterations: q 0..307 processed
        float4 nxt[4];
        #pragma unroll
        for (int j = 0; j < 4; ++j)
            nxt[j] = __ldcs(p4 + (size_t)(base + 4 + j) * (HWC / 4));
        #pragma unroll
        for (int j = 0; j < 4; ++j)
            expacc(buf[j], S01, S23, K);
        #pragma unroll
        for (int j = 0; j < 4; ++j)
            buf[j] = nxt[j];
    }
    #pragma unroll
    for (int j = 0; j < 4; ++j)                      // q 308..311
        expacc(buf[j], S01, S23, K);
    expacc(__ldcs(p4 + (size_t)312 * (HWC / 4)), S01, S23, K);   // q 312

    float S[4];
    upkf(S01, S[0], S[1]);
    upkf(S23, S[2], S[3]);

    float part = 0.f;
    #pragma unroll
    for (int p = 0; p < 4; ++p)
        part += fmaf(coef[p], __logf(S[p]), pre[p]);

    // ---- deterministic block reduction ----
    const int lane = tid & 31, wid = tid >> 5;
    #pragma unroll
    for (int o = 16; o > 0; o >>= 1)
        part += __shfl_down_sync(0xFFFFFFFFu, part, o);
    if (lane == 0) s_red[wid] = part;
    __syncthreads();

    if (tid == 0) {
        float bsum = 0.f;
        #pragma unroll
        for (int w = 0; w < TPB / 32; ++w) bsum += s_red[w];
        g_partial[blockIdx.x] = bsum;
        __threadfence();
        unsigned t = atomicAdd(&g_count, 1u);
        s_last = (t == NBLK - 1);
    }
    __syncthreads();

    if (s_last) {
        float v = 0.f;
        #pragma unroll
        for (int base = 0; base < NBLK; base += TPB)
            if (base + tid < NBLK) v += g_partial[base + tid];
        s_fin[tid] = v;
        __syncthreads();
        #pragma unroll
        for (int s = TPB / 2; s > 0; s >>= 1) {
            if (tid < s) s_fin[tid] += s_fin[tid + s];
            __syncthreads();
        }
        if (tid == 0) {
            out[0] = s_fin[0] * (1.0f / (float)MTOT);
            g_count = 0;   // reset for next graph replay
        }
    }
}

extern "C" void kernel_launch(void* const* d_in, const int* in_sizes, int n_in,
                              void* d_out, int out_size) {
    const float* pred    = (const float*)d_in[0];   // (32,313,96,96)
    const float* tgt     = (const float*)d_in[1];   // (32,2,96,96)
    const float* centers = (const float*)d_in[2];   // (313,2)
    const float* cw      = (const float*)d_in[3];   // (313,)
    (void)in_sizes; (void)n_in; (void)out_size;

    build_grid<<<(NCELL * 32) / 256, 256>>>(centers);
    loss_main<<<NBLK, TPB>>>(pred, tgt, centers, cw, (float*)d_out);
}